// round 3
// baseline (speedup 1.0000x reference)
#include <cuda_runtime.h>

// ============================================================================
// LayerStacks fused kernel, FP32 SIMT baseline.
//
// Key insight: every "[idx]" gather in the reference selects ONE of COUNT=8
// groups per row, so per row we only need:
//   - 16 rows of l1_w (group ls[b]) + 16 rows of l1f_w  (32 dots over K=3072)
//   - 32 of the 256 KAN outputs (cols ls[b]*32..+31)
//   - 1 row of out_w
// We counting-sort rows by group so each block is group-uniform and can keep
// weights + KAN params in SMEM.
// ============================================================================

#define B_MAX  16384
#define TB     128      // rows per block tile
#define KT     32       // K tile
#define KDIM   3072
#define NGRP   8

// -------- scratch (no allocations allowed) --------
__device__ int g_counts[NGRP];
__device__ int g_cursor[NGRP];
__device__ int g_row_off[NGRP + 1];
__device__ int g_tile_off[NGRP + 1];
__device__ int g_perm[B_MAX];

__global__ void k_zero() {
    if (threadIdx.x < NGRP) g_counts[threadIdx.x] = 0;
}

__global__ void k_hist(const int* __restrict__ ls, int B) {
    int i = blockIdx.x * blockDim.x + threadIdx.x;
    for (; i < B; i += gridDim.x * blockDim.x)
        atomicAdd(&g_counts[ls[i]], 1);
}

__global__ void k_prefix() {
    if (threadIdx.x == 0 && blockIdx.x == 0) {
        int s = 0, t = 0;
        for (int g = 0; g < NGRP; g++) {
            g_row_off[g]  = s;
            g_tile_off[g] = t;
            g_cursor[g]   = s;
            s += g_counts[g];
            t += (g_counts[g] + TB - 1) / TB;
        }
        g_row_off[NGRP]  = s;
        g_tile_off[NGRP] = t;
    }
}

__global__ void k_scatter(const int* __restrict__ ls, int B) {
    int i = blockIdx.x * blockDim.x + threadIdx.x;
    for (; i < B; i += gridDim.x * blockDim.x) {
        int pos = atomicAdd(&g_cursor[ls[i]], 1);
        g_perm[pos] = i;
    }
}

// ============================================================================
// Main fused kernel: one block = 128 rows of one group.
// SMEM arena layout (floats):
//   mainloop : xs[128][33] at 0        (4224)   ws[32][33] at 4224 (1056)
//   epilogue : l1[128][33] at 0 (reuse xs)
//              wsp[30][32][6] at 4224  (5760)   (overlaps ws, after sync)
//              sbs[30][32]   at 9984   (960)
// ============================================================================
__global__ void __launch_bounds__(256, 1) k_main(
    const float* __restrict__ x,        const float* __restrict__ l1_w,
    const float* __restrict__ l1_b,     const float* __restrict__ l1f_w,
    const float* __restrict__ l1f_b,    const float* __restrict__ kan_grid,
    const float* __restrict__ kan_coef, const float* __restrict__ ksb,
    const float* __restrict__ ksp,      const float* __restrict__ out_w,
    const float* __restrict__ out_b,    float* __restrict__ out)
{
    __shared__ float sh_big[10944];   // 43776 B
    __shared__ int   sh_rows[TB];
    __shared__ float sh_bias[32];
    __shared__ float sh_outw[32];
    __shared__ float sh_grid[30 * 10];
    __shared__ float sh_rden[30 * 24]; // knot-diff reciprocals: d=1:[0..8] d=2:[9..16] d=3:[17..23]

    const int bid = blockIdx.x, tid = threadIdx.x;

    // ---- which group / tile is this block? ----
    int g = 0;
    #pragma unroll
    for (int i = 0; i < NGRP; i++)
        if (bid >= g_tile_off[i + 1]) g = i + 1;
    if (g >= NGRP) return;   // beyond total tiles (whole block exits)

    const int tile_in_g = bid - g_tile_off[g];
    const int row_start = g_row_off[g] + tile_in_g * TB;
    int nrows = g_row_off[g + 1] - row_start;
    if (nrows > TB) nrows = TB;

    if (tid < TB) {
        int rr = tid < nrows ? tid : (nrows - 1);
        sh_rows[tid] = g_perm[row_start + rr];
    }
    if (tid < 16)            sh_bias[tid] = l1_b[g * 16 + tid];
    else if (tid < 32)       sh_bias[tid] = l1f_b[tid - 16];
    if (tid < 32)            sh_outw[tid] = out_w[g * 32 + tid];
    __syncthreads();

    float* xs = sh_big;          // [128][33]
    float* ws = sh_big + 4224;   // [32][33]

    const int tx = tid & 7;      // col micro-tile: cols 4*tx..4*tx+3
    const int ty = tid >> 3;     // row micro-tile: rows 4*ty..4*ty+3
    const int wid = tid >> 5;    // warp id 0..7
    const int wk  = tid & 31;

    // weight source pointers: cols 0..15 = l1_w group rows, 16..31 = l1f_w
    const float* wptr[4];
    #pragma unroll
    for (int it = 0; it < 4; it++) {
        int c = it * 8 + wid;
        wptr[it] = (c < 16) ? (l1_w + (size_t)(g * 16 + c) * KDIM)
                            : (l1f_w + (size_t)(c - 16) * KDIM);
    }
    const float* xptr[4];
    int xr_[4], xkv[4];
    #pragma unroll
    for (int it = 0; it < 4; it++) {
        int idx = it * 256 + tid;
        xr_[it] = idx >> 3;        // 0..127
        xkv[it] = idx & 7;         // float4 slot 0..7
        xptr[it] = x + (size_t)sh_rows[xr_[it]] * KDIM + xkv[it] * 4;
    }

    // ---- register-prefetched mainloop ----
    float4 xreg[4];
    float  wreg[4];
    #pragma unroll
    for (int it = 0; it < 4; it++) {
        xreg[it] = *(const float4*)(xptr[it]);
        wreg[it] = wptr[it][wk];
    }

    float acc[4][4];
    #pragma unroll
    for (int i = 0; i < 4; i++)
        #pragma unroll
        for (int j = 0; j < 4; j++) acc[i][j] = 0.0f;

    const int NT = KDIM / KT;   // 96
    for (int kt = 0; kt < NT; kt++) {
        __syncthreads();   // previous tile's compute done
        #pragma unroll
        for (int it = 0; it < 4; it++) {
            int base = xr_[it] * 33 + xkv[it] * 4;   // conflict-free scatter
            xs[base + 0] = xreg[it].x;  xs[base + 1] = xreg[it].y;
            xs[base + 2] = xreg[it].z;  xs[base + 3] = xreg[it].w;
            ws[(it * 8 + wid) * 33 + wk] = wreg[it];
        }
        __syncthreads();
        if (kt + 1 < NT) {
            int k0 = (kt + 1) * KT;
            #pragma unroll
            for (int it = 0; it < 4; it++) {
                xreg[it] = *(const float4*)(xptr[it] + k0);
                wreg[it] = wptr[it][k0 + wk];
            }
        }
        #pragma unroll
        for (int kk = 0; kk < KT; kk++) {
            float xv[4], wv[4];
            #pragma unroll
            for (int j = 0; j < 4; j++) {
                xv[j] = xs[(4 * ty + j) * 33 + kk];
                wv[j] = ws[(4 * tx + j) * 33 + kk];
            }
            #pragma unroll
            for (int i = 0; i < 4; i++)
                #pragma unroll
                for (int j = 0; j < 4; j++)
                    acc[i][j] = fmaf(xv[i], wv[j], acc[i][j]);
        }
    }
    __syncthreads();   // all reads of xs done → safe to overwrite

    // ---- deposit l1 tile (+bias) into SMEM: l1[128][33] ----
    #pragma unroll
    for (int i = 0; i < 4; i++)
        #pragma unroll
        for (int j = 0; j < 4; j++)
            xs[(4 * ty + i) * 33 + (4 * tx + j)] = acc[i][j] + sh_bias[4 * tx + j];

    // ---- stage KAN params for this group ----
    float* wsp = sh_big + 4224;          // [30][32][6] = coef * scale_sp
    float* sbs = sh_big + 4224 + 5760;   // [30][32]    = scale_base
    for (int t2 = tid; t2 < 5760; t2 += 256) {
        int k  = t2 % 6;
        int c  = (t2 / 6) & 31;
        int ii = t2 / 192;
        int id2 = ii * 256 + g * 32 + c;
        wsp[t2] = kan_coef[id2 * 6 + k] * ksp[id2];
    }
    for (int t2 = tid; t2 < 960; t2 += 256) {
        int c = t2 & 31, ii = t2 >> 5;
        sbs[t2] = ksb[ii * 256 + g * 32 + c];
    }
    for (int t2 = tid; t2 < 300; t2 += 256) sh_grid[t2] = kan_grid[t2];
    for (int t2 = tid; t2 < 720; t2 += 256) {
        int ii = t2 / 24, j24 = t2 % 24;
        int d, j;
        if (j24 < 9)       { d = 1; j = j24; }
        else if (j24 < 17) { d = 2; j = j24 - 9; }
        else               { d = 3; j = j24 - 17; }
        const float* gr = kan_grid + ii * 10;
        sh_rden[t2] = 1.0f / (gr[j + d] - gr[j]);
    }
    __syncthreads();

    // ---- epilogue: 2 threads per row, 16 KAN cols each ----
    const int r = tid >> 1, h = tid & 1;
    const float* lrow = xs + r * 33;
    const float l1c_out = lrow[15];
    const float l1f_out = lrow[31];

    float a[30];
    #pragma unroll
    for (int i = 0; i < 15; i++) {
        float z = lrow[i] + lrow[16 + i];
        float q = (z * z) * (127.0f / 128.0f);
        a[i]      = fminf(fmaxf(q, 0.0f), 1.0f);
        a[i + 15] = fminf(fmaxf(z, 0.0f), 1.0f);
    }

    float acc2[16];
    #pragma unroll
    for (int c = 0; c < 16; c++) acc2[c] = 0.0f;

    #pragma unroll
    for (int i = 0; i < 30; i++) {
        const float* gr = sh_grid + i * 10;
        const float* rd = sh_rden + i * 24;
        const float xv  = a[i];

        // Cox-de Boor, k=3, matching the reference exactly
        float b[9];
        #pragma unroll
        for (int j = 0; j < 9; j++)
            b[j] = (xv >= gr[j] && xv < gr[j + 1]) ? 1.0f : 0.0f;
        #pragma unroll
        for (int d = 1; d <= 3; d++) {
            const float* rdd = rd + (d == 1 ? 0 : (d == 2 ? 9 : 17));
            #pragma unroll
            for (int j = 0; j <= 8 - d; j++)
                b[j] = (xv - gr[j]) * rdd[j] * b[j]
                     + (gr[j + d + 1] - xv) * rdd[j + 1] * b[j + 1];
        }
        const float s = xv / (1.0f + __expf(-xv));   // silu

        const float* sbp = sbs + i * 32 + h * 16;
        const float* wp  = wsp + (i * 32 + h * 16) * 6;
        #pragma unroll
        for (int c = 0; c < 16; c++) {
            float t = s * sbp[c];
            #pragma unroll
            for (int k = 0; k < 6; k++)
                t = fmaf(b[k], wp[c * 6 + k], t);
            acc2[c] += t;
        }
    }

    float part = 0.0f;
    #pragma unroll
    for (int c = 0; c < 16; c++) {
        float v = fminf(fmaxf(acc2[c], 0.0f), 1.0f);
        part = fmaf(v, sh_outw[h * 16 + c], part);
    }
    part += __shfl_xor_sync(0xffffffffu, part, 1);

    if (h == 0 && r < nrows)
        out[sh_rows[r]] = part + out_b[g] + l1f_out + l1c_out;
}

// ============================================================================
extern "C" void kernel_launch(void* const* d_in, const int* in_sizes, int n_in,
                              void* d_out, int out_size)
{
    const float* x        = (const float*)d_in[0];
    const int*   ls       = (const int*)  d_in[1];
    const float* l1_w     = (const float*)d_in[2];
    const float* l1_b     = (const float*)d_in[3];
    const float* l1f_w    = (const float*)d_in[4];
    const float* l1f_b    = (const float*)d_in[5];
    const float* kan_grid = (const float*)d_in[6];
    const float* kan_coef = (const float*)d_in[7];
    const float* ksb      = (const float*)d_in[8];
    const float* ksp      = (const float*)d_in[9];
    const float* out_w    = (const float*)d_in[10];
    const float* out_b    = (const float*)d_in[11];
    float* out = (float*)d_out;

    int B = in_sizes[1];   // ls_indices element count

    k_zero<<<1, 32>>>();
    k_hist<<<64, 256>>>(ls, B);
    k_prefix<<<1, 1>>>();
    k_scatter<<<64, 256>>>(ls, B);

    int tiles = B / TB + NGRP;   // upper bound on Σ ceil(count_g/TB)
    k_main<<<tiles, 256>>>(x, l1_w, l1_b, l1f_w, l1f_b, kan_grid,
                           kan_coef, ksb, ksp, out_w, out_b, out);
}